// round 16
// baseline (speedup 1.0000x reference)
#include <cuda_runtime.h>
#include <cuda_fp16.h>
#include <math.h>
#include <stdint.h>

// Problem constants
#define NB 100000
#define NC 10000
#define EB 400000
#define EC 80000
#define CAP 64

// halfs -> float slots
#define HF(n) (((n) + 1) / 2)

// ---------------------------------------------------------------------------
// Scratch layout (float units; half/int regions reinterpreted)
// ---------------------------------------------------------------------------
constexpr long long O_CFH   = 0;                                    // h [NC,32]
constexpr long long O_CXLR  = O_CFH   + HF((long long)NC * 32);     // h [NC,1024]
constexpr long long O_CH1   = O_CXLR  + HF((long long)NC * 1024);   // h [NC,512]
constexpr long long O_CXLR2 = O_CH1   + HF((long long)NC * 512);    // h [NC,256]
constexpr long long O_CH2   = O_CXLR2 + HF((long long)NC * 256);    // h [NC,128]
constexpr long long O_WC1T  = O_CH2   + HF((long long)NC * 128);    // h [1024,32]
constexpr long long O_WC2T  = O_WC1T  + HF(1024 * 32);              // h [256,512]
constexpr long long O_WB2T  = O_WC2T  + HF(256 * 512);              // h [256,512]
constexpr long long O_FALO  = O_WB2T  + HF(256 * 512);              // h [1024,64]
constexpr long long O_FAHI  = O_FALO  + HF(1024 * 64);              // h [1024,128]
constexpr long long O_B1LO  = O_FAHI  + HF(1024 * 128);             // h [1024,64]
constexpr long long O_B1HI  = O_B1LO  + HF(1024 * 64);              // h [1024,128]
constexpr long long O_BFH   = O_B1HI  + HF(1024 * 128);             // h [NB,64]
constexpr long long O_WM    = O_BFH   + HF((long long)NB * 64);     // f [NB,2]
constexpr long long O_ZFA   = O_WM    + (long long)NB * 2;          // f [NC,1024]
constexpr long long O_ZB1   = O_ZFA   + (long long)NC * 1024;       // f [NC,1024]
constexpr long long O_BXLR  = O_ZB1   + (long long)NC * 1024;       // h [NB,1024]
constexpr long long O_BH1   = O_BXLR  + HF((long long)NB * 1024);   // h [NB,512]
constexpr long long O_BH2   = O_BH1   + HF((long long)NB * 512);    // h [NB,128]
constexpr long long O_XL3   = O_BH2   + HF((long long)NB * 128);    // f [NB,2]
constexpr long long O_XR3   = O_XL3   + (long long)NB * 2;          // f [NB,2]
constexpr long long O_BCNT  = O_XR3   + (long long)NB * 2;          // i [NB]
constexpr long long O_BEL   = O_BCNT  + (long long)NB;              // i [NB*CAP]
constexpr long long O_CCNT  = O_BEL   + (long long)NB * CAP;        // i [NC]
constexpr long long O_CEL   = O_CCNT  + (long long)NC;              // i [NC*CAP]
constexpr long long SCRATCH_TOTAL = O_CEL + (long long)NC * CAP + 64;

__device__ float g_scratch[SCRATCH_TOTAL];

// ---------------------------------------------------------------------------
__global__ void zero_misc(int* __restrict__ bcnt, int* __restrict__ ccnt,
                          float* __restrict__ wm)
{
    int i = blockIdx.x * blockDim.x + threadIdx.x;
    if (i < NB) bcnt[i] = 0;
    if (i < NC) ccnt[i] = 0;
    if (i < 2 * NB) wm[i] = 0.0f;
}

// ---------------------------------------------------------------------------
// ONE prep kernel: all fp32->fp16 conversions and weight transposes.
// ---------------------------------------------------------------------------
__device__ __forceinline__ __half pairT_elem(const float* a, const float* b,
                                             int i, int K, int M, int k0)
{
    int m = i / K, k = i % K;
    float v = (m < M) ? a[(long long)(k0 + k) * M + m]
                      : b[(long long)(k0 + k) * M + (m - M)];
    return __float2half(v);
}

__device__ __forceinline__ __half faT_elem(const float* w, int i, int K, int k0)
{
    int m = i / K, k = i % K;
    int h = m >> 7, j = m & 127;
    return __float2half(w[(long long)h * 192 * 128 + (long long)(k0 + k) * 128 + j]);
}

#define SEG0 ((long long)NB * 64)
#define SEG1 ((long long)NC * 32)
#define SEG2 (1024LL * 32)
#define SEG3 (256LL * 512)
#define SEG4 (256LL * 512)
#define SEG5 (1024LL * 64)
#define SEG6 (1024LL * 128)
#define SEG7 (1024LL * 64)
#define SEG8 (1024LL * 128)
#define PREP_TOTAL (SEG0+SEG1+SEG2+SEG3+SEG4+SEG5+SEG6+SEG7+SEG8)

__global__ void prep_all(const float* __restrict__ bf, const float* __restrict__ cf,
                         const float* __restrict__ c1wl, const float* __restrict__ c1wr,
                         const float* __restrict__ c2wl, const float* __restrict__ c2wr,
                         const float* __restrict__ b2wl, const float* __restrict__ b2wr,
                         const float* __restrict__ faw1,
                         const float* __restrict__ b1wl, const float* __restrict__ b1wr,
                         __half* __restrict__ bfh, __half* __restrict__ cfh,
                         __half* __restrict__ wc1t, __half* __restrict__ wc2t,
                         __half* __restrict__ wb2t,
                         __half* __restrict__ faLo, __half* __restrict__ faHi,
                         __half* __restrict__ b1Lo, __half* __restrict__ b1Hi)
{
    long long i = (long long)blockIdx.x * blockDim.x + threadIdx.x;
    if (i < SEG0) { bfh[i] = __float2half(bf[i]); return; }
    i -= SEG0;
    if (i < SEG1) { cfh[i] = __float2half(cf[i]); return; }
    i -= SEG1;
    if (i < SEG2) { wc1t[i] = pairT_elem(c1wl, c1wr, (int)i, 32, 512, 0); return; }
    i -= SEG2;
    if (i < SEG3) { wc2t[i] = pairT_elem(c2wl, c2wr, (int)i, 512, 128, 0); return; }
    i -= SEG3;
    if (i < SEG4) { wb2t[i] = pairT_elem(b2wl, b2wr, (int)i, 512, 128, 0); return; }
    i -= SEG4;
    if (i < SEG5) { faLo[i] = faT_elem(faw1, (int)i, 64, 0); return; }
    i -= SEG5;
    if (i < SEG6) { faHi[i] = faT_elem(faw1, (int)i, 128, 64); return; }
    i -= SEG6;
    if (i < SEG7) { b1Lo[i] = pairT_elem(b1wl, b1wr, (int)i, 64, 512, 0); return; }
    i -= SEG7;
    if (i < SEG8) { b1Hi[i] = pairT_elem(b1wl, b1wr, (int)i, 128, 512, 64); return; }
}

// Bucket lists store SRC node ids directly.
__global__ void build_lists(const int* __restrict__ ei, int E,
                            int* __restrict__ cnt, int* __restrict__ el)
{
    int e = blockIdx.x * blockDim.x + threadIdx.x;
    if (e >= E) return;
    int s = ei[e];
    int d = ei[E + e];
    int slot = atomicAdd(&cnt[d], 1);
    if (slot < CAP) el[(long long)d * CAP + slot] = s;
}

// ---------------------------------------------------------------------------
// FP16 tensor-core GEMM, m16n8k16, 4-stage cp.async pipeline, ldmatrix frags.
// C[N,M] = A[N,K] @ B^T  (B passed TRANSPOSED as [M,K] fp16, k contiguous)
// 128x128x32 CTA tile, 8 warps, warp tile 64x32.
// MODE 0: plain store (+bias, optional relu). CHALF: store fp16 vs fp32.
// MODE 1 (fa): epilogue v = relu(acc + Z[map[row]][col] + bias[col]);
//   head-reduce vs w2; softmax(+b2); atomicAdd 0.125*softmax into wmean.
// MODE 2 (b1): A fragments scaled by ascale[row*2+0] (half2 mul);
//   store C = acc + ascale[row*2+1] * Z[map[row]][col] (fp16).
// ---------------------------------------------------------------------------
#define ATILE_B (128 * 80)
#define BTILE_B (128 * 80)
#define BUF_B (ATILE_B + BTILE_B)
#define STAGES 4
#define GEMM_SMEM_BYTES (STAGES * BUF_B)   // 81920

__device__ __forceinline__ void cp16(uint32_t d, const void* s, bool pred) {
    int sz = pred ? 16 : 0;
    asm volatile("cp.async.ca.shared.global [%0], [%1], 16, %2;\n"
                 :: "r"(d), "l"(s), "r"(sz));
}

__device__ __forceinline__ void mma16(float* c, unsigned a0, unsigned a1,
                                      unsigned a2, unsigned a3,
                                      unsigned b0, unsigned b1) {
    asm volatile(
        "mma.sync.aligned.m16n8k16.row.col.f32.f16.f16.f32 "
        "{%0,%1,%2,%3},{%4,%5,%6,%7},{%8,%9},{%0,%1,%2,%3};"
        : "+f"(c[0]), "+f"(c[1]), "+f"(c[2]), "+f"(c[3])
        : "r"(a0), "r"(a1), "r"(a2), "r"(a3), "r"(b0), "r"(b1));
}

__device__ __forceinline__ void ldsm4(unsigned& r0, unsigned& r1,
                                      unsigned& r2, unsigned& r3, uint32_t addr) {
    asm volatile("ldmatrix.sync.aligned.m8n8.x4.shared.b16 {%0,%1,%2,%3}, [%4];"
                 : "=r"(r0), "=r"(r1), "=r"(r2), "=r"(r3) : "r"(addr));
}

__device__ __forceinline__ unsigned hmul2u(unsigned a, __half2 s) {
    __half2 v = __hmul2(*reinterpret_cast<__half2*>(&a), s);
    return *reinterpret_cast<unsigned*>(&v);
}

template<int MODE, bool CHALF>
__global__ void __launch_bounds__(256, 2) hgemm(
    const __half* __restrict__ A, const __half* __restrict__ B,
    void* __restrict__ Cv, const float* __restrict__ bias,
    int N, int K, int M, int relu,
    const float* __restrict__ w2, const float* __restrict__ b2,
    float* __restrict__ wmean,
    const float* __restrict__ zsrc,    // fp32 [NC, M] (MODE 1/2)
    const int*   __restrict__ gmap,    // [N]          (MODE 1/2)
    const float* __restrict__ ascale)  // fp32 [N,2]   (MODE 2)
{
    extern __shared__ char smc[];
    int tid = threadIdx.x;
    int warp = tid >> 5, lane = tid & 31;
    int wm = (warp >> 2) * 64;
    int wn = (warp & 3) * 32;
    int g  = lane >> 2;
    int tg = lane & 3;
    int rowBase = blockIdx.y * 128;
    int colBase = blockIdx.x * 128;

    uint32_t sbase = (uint32_t)__cvta_generic_to_shared(smc);

    int lrow = lane & 7, seg = lane >> 3;
    uint32_t aLane = (uint32_t)((wm + (seg & 1) * 8 + lrow) * 80 + ((seg >> 1) & 1) * 16);
    uint32_t bLane = (uint32_t)((wn + (seg >> 1) * 8 + lrow) * 80 + (seg & 1) * 16);

    float acc[4][4][4] = {};
    int T = K >> 5;

    // MODE 2: per-row wm0 scales as broadcast half2 (rows g and g+8 per mi)
    __half2 sc0[4], sc1[4];
    if (MODE == 2) {
        #pragma unroll
        for (int mi = 0; mi < 4; mi++) {
            int r0 = rowBase + wm + mi * 16 + g;
            int r1 = r0 + 8;
            sc0[mi] = __float2half2_rn(r0 < N ? ascale[(long long)r0 * 2] : 0.0f);
            sc1[mi] = __float2half2_rn(r1 < N ? ascale[(long long)r1 * 2] : 0.0f);
        }
    }

    auto issue_tile = [&](int k0, int buf) {
        uint32_t ab = sbase + (uint32_t)(buf * BUF_B);
        uint32_t bb = ab + ATILE_B;
        #pragma unroll
        for (int it = 0; it < 2; it++) {
            int c = tid + it * 256;
            int r  = c >> 2;
            int kc = (c & 3) << 3;
            int gr = rowBase + r;
            bool pa = gr < N;
            cp16(ab + (uint32_t)(r * 80 + kc * 2),
                 A + (long long)(pa ? gr : 0) * K + k0 + kc, pa);
            int n = colBase + r;
            cp16(bb + (uint32_t)(r * 80 + kc * 2),
                 B + (long long)n * K + k0 + kc, true);
        }
        asm volatile("cp.async.commit_group;\n");
    };

    issue_tile(0, 0);
    if (T > 1) issue_tile(32, 1);
    if (T > 2) issue_tile(64, 2);

    for (int t = 0; t < T; t++) {
        if (t + 2 < T)      { asm volatile("cp.async.wait_group 2;\n"); }
        else if (t + 1 < T) { asm volatile("cp.async.wait_group 1;\n"); }
        else                { asm volatile("cp.async.wait_group 0;\n"); }
        __syncthreads();
        if (t + 3 < T) issue_tile((t + 3) << 5, (t + 3) % STAGES);

        uint32_t ab = sbase + (uint32_t)((t % STAGES) * BUF_B);
        uint32_t aAddr = ab + aLane;
        uint32_t bAddr = ab + ATILE_B + bLane;

        #pragma unroll
        for (int ks = 0; ks < 32; ks += 16) {
            unsigned aF[4][4], bF[4][2];
            #pragma unroll
            for (int mi = 0; mi < 4; mi++) {
                ldsm4(aF[mi][0], aF[mi][1], aF[mi][2], aF[mi][3],
                      aAddr + (uint32_t)(mi * 16 * 80 + ks * 2));
                if (MODE == 2) {
                    aF[mi][0] = hmul2u(aF[mi][0], sc0[mi]);
                    aF[mi][1] = hmul2u(aF[mi][1], sc1[mi]);
                    aF[mi][2] = hmul2u(aF[mi][2], sc0[mi]);
                    aF[mi][3] = hmul2u(aF[mi][3], sc1[mi]);
                }
            }
            #pragma unroll
            for (int p = 0; p < 2; p++)
                ldsm4(bF[2 * p][0], bF[2 * p][1], bF[2 * p + 1][0], bF[2 * p + 1][1],
                      bAddr + (uint32_t)(p * 16 * 80 + ks * 2));
            #pragma unroll
            for (int mi = 0; mi < 4; mi++)
                #pragma unroll
                for (int nj = 0; nj < 4; nj++)
                    mma16(acc[mi][nj], aF[mi][0], aF[mi][1], aF[mi][2], aF[mi][3],
                          bF[nj][0], bF[nj][1]);
        }
    }

    if (MODE != 1) {
        #pragma unroll
        for (int mi = 0; mi < 4; mi++) {
            int row = rowBase + wm + mi * 16 + g;
            const float* z0p = nullptr; const float* z1p = nullptr;
            float w1a = 0.f, w1b = 0.f;
            if (MODE == 2) {
                if (row < N)     { z0p = zsrc + (long long)gmap[row] * M;
                                   w1a = ascale[(long long)row * 2 + 1]; }
                if (row + 8 < N) { z1p = zsrc + (long long)gmap[row + 8] * M;
                                   w1b = ascale[(long long)(row + 8) * 2 + 1]; }
            }
            #pragma unroll
            for (int nj = 0; nj < 4; nj++) {
                int col = colBase + wn + nj * 8 + tg * 2;
                float b0 = 0.f, b1 = 0.f;
                if (bias) { b0 = bias[col]; b1 = bias[col + 1]; }
                if (row < N) {
                    float vx = acc[mi][nj][0] + b0, vy = acc[mi][nj][1] + b1;
                    if (MODE == 2) {
                        float2 zv = *(const float2*)(z0p + col);
                        vx += w1a * zv.x; vy += w1a * zv.y;
                    }
                    if (relu) { vx = fmaxf(vx, 0.f); vy = fmaxf(vy, 0.f); }
                    if (CHALF) *(__half2*)((__half*)Cv + (long long)row * M + col) =
                                   __floats2half2_rn(vx, vy);
                    else       *(float2*)((float*)Cv + (long long)row * M + col) =
                                   make_float2(vx, vy);
                }
                if (row + 8 < N) {
                    float vx = acc[mi][nj][2] + b0, vy = acc[mi][nj][3] + b1;
                    if (MODE == 2) {
                        float2 zv = *(const float2*)(z1p + col);
                        vx += w1b * zv.x; vy += w1b * zv.y;
                    }
                    if (relu) { vx = fmaxf(vx, 0.f); vy = fmaxf(vy, 0.f); }
                    if (CHALF) *(__half2*)((__half*)Cv + (long long)(row + 8) * M + col) =
                                   __floats2half2_rn(vx, vy);
                    else       *(float2*)((float*)Cv + (long long)(row + 8) * M + col) =
                                   make_float2(vx, vy);
                }
            }
        }
    } else {
        // fa-head epilogue with Z add. head = blockIdx.x.
        int h = blockIdx.x;
        float* srow = (float*)smc;
        __syncthreads();
        for (int i = tid; i < 256; i += 256) srow[i] = 0.0f;
        __syncthreads();

        #pragma unroll
        for (int mi = 0; mi < 4; mi++) {
            #pragma unroll
            for (int hf = 0; hf < 2; hf++) {
                int rrel = wm + mi * 16 + g + 8 * hf;
                int row = rowBase + rrel;
                if (row >= N) continue;
                const float* zrow = zsrc + (long long)gmap[row] * M + colBase;
                float p0 = 0.f, p1 = 0.f;
                #pragma unroll
                for (int nj = 0; nj < 4; nj++) {
                    int cr = wn + nj * 8 + tg * 2;
                    float a0 = acc[mi][nj][2 * hf];
                    float a1 = acc[mi][nj][2 * hf + 1];
                    float v0 = fmaxf(a0 + zrow[cr] + bias[colBase + cr], 0.f);
                    float v1 = fmaxf(a1 + zrow[cr + 1] + bias[colBase + cr + 1], 0.f);
                    float2 wa = *(const float2*)(w2 + h * 256 + cr * 2);
                    float2 wb = *(const float2*)(w2 + h * 256 + (cr + 1) * 2);
                    p0 += v0 * wa.x + v1 * wb.x;
                    p1 += v0 * wa.y + v1 * wb.y;
                }
                atomicAdd(&srow[rrel * 2 + 0], p0);
                atomicAdd(&srow[rrel * 2 + 1], p1);
            }
        }
        __syncthreads();
        if (tid < 128) {
            int grow = rowBase + tid;
            if (grow < N) {
                float sa = srow[tid * 2 + 0] + b2[h * 2 + 0];
                float sb = srow[tid * 2 + 1] + b2[h * 2 + 1];
                float mx = fmaxf(sa, sb);
                float e0 = expf(sa - mx), e1 = expf(sb - mx);
                float inv = 0.125f / (e0 + e1);
                atomicAdd(&wmean[(long long)grow * 2 + 0], e0 * inv);
                atomicAdd(&wmean[(long long)grow * 2 + 1], e1 * inv);
            }
        }
    }
}

// ---------------------------------------------------------------------------
// Fused GATv2 softmax+aggregate, fp16 in/out, online softmax, 4 halfs/lane.
// ---------------------------------------------------------------------------
template<int LPG, int D, int H, bool RELU>
__global__ void gat_fused(const int* __restrict__ cnt, const int* __restrict__ el,
                          const __half* __restrict__ xl, const __half* __restrict__ xr,
                          int ldx,
                          const float* __restrict__ att, const float* __restrict__ bias,
                          __half* __restrict__ out, int Nnodes)
{
    static_assert(D == 4 * LPG, "");
    long long t = (long long)blockIdx.x * blockDim.x + threadIdx.x;
    long long gidx = t / LPG;
    int lane = (int)(t % LPG);
    if (gidx >= (long long)Nnodes * H) return;
    int dst = (int)(gidx / H), h = (int)(gidx % H);

    long long roff = (long long)dst * ldx + h * D + lane * 4;
    uint2 ur = *(const uint2*)(xr + roff);
    float2 xr01 = __half22float2(*reinterpret_cast<__half2*>(&ur.x));
    float2 xr23 = __half22float2(*reinterpret_cast<__half2*>(&ur.y));
    float4 a4  = *(const float4*)(att + (long long)h * D + lane * 4);

    int c = cnt[dst]; if (c > CAP) c = CAP;
    const int* lst = el + (long long)dst * CAP;

    float mx = -1e30f, wsum = 0.0f;
    float4 acc = make_float4(0.f, 0.f, 0.f, 0.f);

    for (int i = 0; i <= c; i++) {
        int src = (i == c) ? dst : lst[i];
        uint2 uv = *(const uint2*)(xl + (long long)src * ldx + h * D + lane * 4);
        float2 v01 = __half22float2(*reinterpret_cast<__half2*>(&uv.x));
        float2 v23 = __half22float2(*reinterpret_cast<__half2*>(&uv.y));
        float e0 = v01.x + xr01.x; e0 = e0 > 0.f ? e0 : 0.2f * e0;
        float e1 = v01.y + xr01.y; e1 = e1 > 0.f ? e1 : 0.2f * e1;
        float e2 = v23.x + xr23.x; e2 = e2 > 0.f ? e2 : 0.2f * e2;
        float e3 = v23.y + xr23.y; e3 = e3 > 0.f ? e3 : 0.2f * e3;
        float s = e0 * a4.x + e1 * a4.y + e2 * a4.z + e3 * a4.w;
        #pragma unroll
        for (int o = LPG / 2; o; o >>= 1) s += __shfl_xor_sync(0xffffffffu, s, o, LPG);
        if (s > mx) {
            float f = expf(mx - s);
            wsum *= f;
            acc.x *= f; acc.y *= f; acc.z *= f; acc.w *= f;
            mx = s;
        }
        float p = expf(s - mx);
        wsum += p;
        acc.x += p * v01.x; acc.y += p * v01.y; acc.z += p * v23.x; acc.w += p * v23.y;
    }

    float inv = 1.0f / wsum;
    const float* pb = bias + h * D + lane * 4;
    float o0 = acc.x * inv + pb[0];
    float o1 = acc.y * inv + pb[1];
    float o2 = acc.z * inv + pb[2];
    float o3 = acc.w * inv + pb[3];
    if (RELU) {
        o0 = fmaxf(o0, 0.f); o1 = fmaxf(o1, 0.f);
        o2 = fmaxf(o2, 0.f); o3 = fmaxf(o3, 0.f);
    }
    __half2 h01 = __floats2half2_rn(o0, o1);
    __half2 h23 = __floats2half2_rn(o2, o3);
    uint2 uo;
    uo.x = *reinterpret_cast<unsigned*>(&h01);
    uo.y = *reinterpret_cast<unsigned*>(&h23);
    *(uint2*)(out + ((long long)dst * H + h) * D + lane * 4) = uo;
}

// Layer 3 (H=1, D=2) fused with final log-softmax, writes d_out (fp32).
__global__ void gat3_lsm(const int* __restrict__ cnt, const int* __restrict__ el,
                         const float* __restrict__ xl, const float* __restrict__ xr,
                         const float* __restrict__ att, const float* __restrict__ bias,
                         float* __restrict__ out, int Nnodes)
{
    long long t = (long long)blockIdx.x * blockDim.x + threadIdx.x;
    long long gidx = t >> 1;
    int lane = (int)(t & 1);
    if (gidx >= Nnodes) return;
    int dst = (int)gidx;

    float xr_d = xr[(long long)dst * 2 + lane];
    float a_d  = att[lane];
    int c = cnt[dst]; if (c > CAP) c = CAP;
    const int* lst = el + (long long)dst * CAP;

    float mx = -1e30f, wsum = 0.0f, acc = 0.0f;
    for (int i = 0; i <= c; i++) {
        int src = (i == c) ? dst : lst[i];
        float xv = xl[(long long)src * 2 + lane];
        float v = xv + xr_d;
        v = v > 0.0f ? v : 0.2f * v;
        float s = v * a_d;
        s += __shfl_xor_sync(0xffffffffu, s, 1, 2);
        if (s > mx) {
            float f = expf(mx - s);
            wsum *= f; acc *= f; mx = s;
        }
        float p = expf(s - mx);
        wsum += p;
        acc += p * xv;
    }
    float v = acc / wsum + bias[lane];
    float o = __shfl_xor_sync(0xffffffffu, v, 1, 2);
    float m2 = fmaxf(v, o);
    float lse = m2 + logf(expf(v - m2) + expf(o - m2));
    out[(long long)dst * 2 + lane] = v - lse;
}

// ---------------------------------------------------------------------------
// layer-3 transforms, 8 lanes per node (coalesced): [N,128] fp16 @ [128,2]x2
__global__ void small_xform8(const __half* __restrict__ x, const float* __restrict__ wl,
                             const float* __restrict__ wr, float* __restrict__ xl,
                             float* __restrict__ xr, int N)
{
    long long t = (long long)blockIdx.x * blockDim.x + threadIdx.x;
    long long n = t >> 3;
    int l = (int)(t & 7);
    if (n >= N) return;
    const __half* px = x + n * 128 + l * 16;
    float a0 = 0, a1 = 0, b0 = 0, b1 = 0;
    #pragma unroll
    for (int k = 0; k < 16; k++) {
        float v = __half2float(px[k]);
        int kk = l * 16 + k;
        a0 += v * wl[kk * 2]; a1 += v * wl[kk * 2 + 1];
        b0 += v * wr[kk * 2]; b1 += v * wr[kk * 2 + 1];
    }
    #pragma unroll
    for (int o = 4; o; o >>= 1) {
        a0 += __shfl_xor_sync(0xffffffffu, a0, o, 8);
        a1 += __shfl_xor_sync(0xffffffffu, a1, o, 8);
        b0 += __shfl_xor_sync(0xffffffffu, b0, o, 8);
        b1 += __shfl_xor_sync(0xffffffffu, b1, o, 8);
    }
    if (l == 0) {
        xl[n * 2] = a0; xl[n * 2 + 1] = a1;
        xr[n * 2] = b0; xr[n * 2 + 1] = b1;
    }
}

// ---------------------------------------------------------------------------
static inline int cdivll(long long a, long long b) { return (int)((a + b - 1) / b); }

extern "C" void kernel_launch(void* const* d_in, const int* in_sizes, int n_in,
                              void* d_out, int out_size)
{
    int idx_bf = 0, idx_cf = 1, idx_bei, idx_cei, idx_map, base_w;
    if (in_sizes[2] == 2 * EB) { idx_bei = 2; idx_cei = 3; idx_map = 4; base_w = 5; }
    else                       { base_w = 2; idx_bei = 26; idx_cei = 27; idx_map = 28; }
    const float* bf  = (const float*)d_in[idx_bf];
    const float* cf  = (const float*)d_in[idx_cf];
    const int*   bei = (const int*)d_in[idx_bei];
    const int*   cei = (const int*)d_in[idx_cei];
    const int*   b2c = (const int*)d_in[idx_map];

    enum { C1WL, C1WR, C1ATT, C1B, C2WL, C2WR, C2ATT, C2B,
           FAW1, FAB1, FAW2, FAB2,
           B1WL, B1WR, B1ATT, B1B, B2WL, B2WR, B2ATT, B2B,
           B3WL, B3WR, B3ATT, B3B };
    const float* W[24];
    for (int i = 0; i < 24; i++) W[i] = (const float*)d_in[base_w + i];

    float* S;
    cudaGetSymbolAddress((void**)&S, g_scratch);
    cudaFuncSetAttribute(hgemm<0, true>,  cudaFuncAttributeMaxDynamicSharedMemorySize, GEMM_SMEM_BYTES);
    cudaFuncSetAttribute(hgemm<0, false>, cudaFuncAttributeMaxDynamicSharedMemorySize, GEMM_SMEM_BYTES);
    cudaFuncSetAttribute(hgemm<1, false>, cudaFuncAttributeMaxDynamicSharedMemorySize, GEMM_SMEM_BYTES);
    cudaFuncSetAttribute(hgemm<2, true>,  cudaFuncAttributeMaxDynamicSharedMemorySize, GEMM_SMEM_BYTES);

    __half* cfh   = (__half*)(S + O_CFH);
    __half* c_xlr = (__half*)(S + O_CXLR);
    __half* c_h1  = (__half*)(S + O_CH1);
    __half* c_xlr2= (__half*)(S + O_CXLR2);
    __half* c_h2  = (__half*)(S + O_CH2);
    __half* Wc1t  = (__half*)(S + O_WC1T);
    __half* Wc2t  = (__half*)(S + O_WC2T);
    __half* Wb2t  = (__half*)(S + O_WB2T);
    __half* faLo  = (__half*)(S + O_FALO);
    __half* faHi  = (__half*)(S + O_FAHI);
    __half* b1Lo  = (__half*)(S + O_B1LO);
    __half* b1Hi  = (__half*)(S + O_B1HI);
    __half* bfh   = (__half*)(S + O_BFH);
    float*  wmean = S + O_WM;
    float*  Zfa   = S + O_ZFA;
    float*  Zb1   = S + O_ZB1;
    __half* b_xlr = (__half*)(S + O_BXLR);
    __half* b_h1  = (__half*)(S + O_BH1);
    __half* b_h2  = (__half*)(S + O_BH2);
    float*  xl3   = S + O_XL3;
    float*  xr3   = S + O_XR3;
    int* bcnt = (int*)(S + O_BCNT);
    int* bel  = (int*)(S + O_BEL);
    int* ccnt = (int*)(S + O_CCNT);
    int* cel  = (int*)(S + O_CEL);

    // ---- Zeroing + graph prep + ALL weight/feature prep ----
    zero_misc<<<cdivll(2 * NB, 256), 256>>>(bcnt, ccnt, wmean);
    build_lists<<<cdivll(EC, 256), 256>>>(cei, EC, ccnt, cel);
    build_lists<<<cdivll(EB, 256), 256>>>(bei, EB, bcnt, bel);
    prep_all<<<cdivll(PREP_TOTAL, 256), 256>>>(
        bf, cf, W[C1WL], W[C1WR], W[C2WL], W[C2WR], W[B2WL], W[B2WR],
        W[FAW1], W[B1WL], W[B1WR],
        bfh, cfh, Wc1t, Wc2t, Wb2t, faLo, faHi, b1Lo, b1Hi);

    // ---- Community GNN ----
    {
        dim3 grid(1024 / 128, (NC + 127) / 128);
        hgemm<0, true><<<grid, 256, GEMM_SMEM_BYTES>>>(
            cfh, Wc1t, c_xlr, nullptr, NC, 32, 1024, 0,
            nullptr, nullptr, nullptr, nullptr, nullptr, nullptr);
    }
    gat_fused<16, 64, 8, true><<<cdivll((long long)NC * 8 * 16, 256), 256>>>(
        ccnt, cel, c_xlr, c_xlr + 512, 1024, W[C1ATT], W[C1B], c_h1, NC);

    {
        dim3 grid(256 / 128, (NC + 127) / 128);
        hgemm<0, true><<<grid, 256, GEMM_SMEM_BYTES>>>(
            c_h1, Wc2t, c_xlr2, nullptr, NC, 512, 256, 0,
            nullptr, nullptr, nullptr, nullptr, nullptr, nullptr);
    }
    gat_fused<8, 32, 4, true><<<cdivll((long long)NC * 4 * 8, 256), 256>>>(
        ccnt, cel, c_xlr2, c_xlr2 + 128, 256, W[C2ATT], W[C2B], c_h2, NC);

    // ---- Low-rank precompute: Z = c_h2 @ W_hi (fp32 out) ----
    {
        dim3 grid(1024 / 128, (NC + 127) / 128);
        hgemm<0, false><<<grid, 256, GEMM_SMEM_BYTES>>>(
            c_h2, faHi, Zfa, nullptr, NC, 128, 1024, 0,
            nullptr, nullptr, nullptr, nullptr, nullptr, nullptr);
        hgemm<0, false><<<grid, 256, GEMM_SMEM_BYTES>>>(
            c_h2, b1Hi, Zb1, nullptr, NC, 128, 1024, 0,
            nullptr, nullptr, nullptr, nullptr, nullptr, nullptr);
    }

    // ---- Feature attention: acc = bfh @ faLo; epilogue adds Zfa[map] ----
    {
        dim3 grid(1024 / 128, (NB + 127) / 128);
        hgemm<1, false><<<grid, 256, GEMM_SMEM_BYTES>>>(
            bfh, faLo, nullptr, W[FAB1], NB, 64, 1024, 1,
            W[FAW2], W[FAB2], wmean, Zfa, b2c, nullptr);
    }

    // ---- Building GNN (b1: A = bfh scaled by wm0 in-fragment) ----
    {
        dim3 grid(1024 / 128, (NB + 127) / 128);
        hgemm<2, true><<<grid, 256, GEMM_SMEM_BYTES>>>(
            bfh, b1Lo, b_xlr, nullptr, NB, 64, 1024, 0,
            nullptr, nullptr, nullptr, Zb1, b2c, wmean);
    }
    gat_fused<16, 64, 8, true><<<cdivll((long long)NB * 8 * 16, 256), 256>>>(
        bcnt, bel, b_xlr, b_xlr + 512, 1024, W[B1ATT], W[B1B], b_h1, NB);

    {
        dim3 grid(256 / 128, (NB + 127) / 128);
        hgemm<0, true><<<grid, 256, GEMM_SMEM_BYTES>>>(
            b_h1, Wb2t, b_xlr, nullptr, NB, 512, 256, 0,
            nullptr, nullptr, nullptr, nullptr, nullptr, nullptr);
    }
    gat_fused<8, 32, 4, true><<<cdivll((long long)NB * 4 * 8, 256), 256>>>(
        bcnt, bel, b_xlr, b_xlr + 128, 256, W[B2ATT], W[B2B], b_h2, NB);

    small_xform8<<<cdivll((long long)NB * 8, 256), 256>>>(b_h2, W[B3WL], W[B3WR], xl3, xr3, NB);
    gat3_lsm<<<cdivll((long long)NB * 2, 256), 256>>>(
        bcnt, bel, xl3, xr3, W[B3ATT], W[B3B], (float*)d_out, NB);
}

// round 17
// speedup vs baseline: 1.4793x; 1.4793x over previous
#include <cuda_runtime.h>
#include <cuda_fp16.h>
#include <math.h>
#include <stdint.h>

// Problem constants
#define NB 100000
#define NC 10000
#define EB 400000
#define EC 80000
#define CAP 64

// halfs -> float slots
#define HF(n) (((n) + 1) / 2)

// ---------------------------------------------------------------------------
// Scratch layout (float units; half/int regions reinterpreted)
// ---------------------------------------------------------------------------
constexpr long long O_CFH   = 0;                                    // h [NC,32]
constexpr long long O_CXLR  = O_CFH   + HF((long long)NC * 32);     // h [NC,1024]
constexpr long long O_CH1   = O_CXLR  + HF((long long)NC * 1024);   // h [NC,512]
constexpr long long O_CXLR2 = O_CH1   + HF((long long)NC * 512);    // h [NC,256]
constexpr long long O_CH2   = O_CXLR2 + HF((long long)NC * 256);    // h [NC,128]
constexpr long long O_WC1T  = O_CH2   + HF((long long)NC * 128);    // h [1024,32]
constexpr long long O_WC2T  = O_WC1T  + HF(1024 * 32);              // h [256,512]
constexpr long long O_WB2T  = O_WC2T  + HF(256 * 512);              // h [256,512]
constexpr long long O_FALO  = O_WB2T  + HF(256 * 512);              // h [1024,64]
constexpr long long O_FAHI  = O_FALO  + HF(1024 * 64);              // h [1024,128]
constexpr long long O_B1LO  = O_FAHI  + HF(1024 * 128);             // h [1024,64]
constexpr long long O_B1HI  = O_B1LO  + HF(1024 * 64);              // h [1024,128]
constexpr long long O_BFH   = O_B1HI  + HF(1024 * 128);             // h [NB,64]
constexpr long long O_WM    = O_BFH   + HF((long long)NB * 64);     // f [NB,2]
constexpr long long O_ZFA   = O_WM    + (long long)NB * 2;          // f [NC,1024]
constexpr long long O_ZB1   = O_ZFA   + (long long)NC * 1024;       // f [NC,1024]
constexpr long long O_BXLR  = O_ZB1   + (long long)NC * 1024;       // h [NB,1024]
constexpr long long O_BH1   = O_BXLR  + HF((long long)NB * 1024);   // h [NB,512]
constexpr long long O_BH2   = O_BH1   + HF((long long)NB * 512);    // h [NB,128]
constexpr long long O_XL3   = O_BH2   + HF((long long)NB * 128);    // f [NB,2]
constexpr long long O_XR3   = O_XL3   + (long long)NB * 2;          // f [NB,2]
constexpr long long O_BCNT  = O_XR3   + (long long)NB * 2;          // i [NB]
constexpr long long O_BEL   = O_BCNT  + (long long)NB;              // i [NB*CAP]
constexpr long long O_CCNT  = O_BEL   + (long long)NB * CAP;        // i [NC]
constexpr long long O_CEL   = O_CCNT  + (long long)NC;              // i [NC*CAP]
constexpr long long SCRATCH_TOTAL = O_CEL + (long long)NC * CAP + 64;

__device__ float g_scratch[SCRATCH_TOTAL];

// ---------------------------------------------------------------------------
__global__ void zero_misc(int* __restrict__ bcnt, int* __restrict__ ccnt,
                          float* __restrict__ wm)
{
    int i = blockIdx.x * blockDim.x + threadIdx.x;
    if (i < NB) bcnt[i] = 0;
    if (i < NC) ccnt[i] = 0;
    if (i < 2 * NB) wm[i] = 0.0f;
}

// ---------------------------------------------------------------------------
// ONE prep kernel: all fp32->fp16 conversions and weight transposes.
// ---------------------------------------------------------------------------
__device__ __forceinline__ __half pairT_elem(const float* a, const float* b,
                                             int i, int K, int M, int k0)
{
    int m = i / K, k = i % K;
    float v = (m < M) ? a[(long long)(k0 + k) * M + m]
                      : b[(long long)(k0 + k) * M + (m - M)];
    return __float2half(v);
}

__device__ __forceinline__ __half faT_elem(const float* w, int i, int K, int k0)
{
    int m = i / K, k = i % K;
    int h = m >> 7, j = m & 127;
    return __float2half(w[(long long)h * 192 * 128 + (long long)(k0 + k) * 128 + j]);
}

#define SEG0 ((long long)NB * 64)
#define SEG1 ((long long)NC * 32)
#define SEG2 (1024LL * 32)
#define SEG3 (256LL * 512)
#define SEG4 (256LL * 512)
#define SEG5 (1024LL * 64)
#define SEG6 (1024LL * 128)
#define SEG7 (1024LL * 64)
#define SEG8 (1024LL * 128)
#define PREP_TOTAL (SEG0+SEG1+SEG2+SEG3+SEG4+SEG5+SEG6+SEG7+SEG8)

__global__ void prep_all(const float* __restrict__ bf, const float* __restrict__ cf,
                         const float* __restrict__ c1wl, const float* __restrict__ c1wr,
                         const float* __restrict__ c2wl, const float* __restrict__ c2wr,
                         const float* __restrict__ b2wl, const float* __restrict__ b2wr,
                         const float* __restrict__ faw1,
                         const float* __restrict__ b1wl, const float* __restrict__ b1wr,
                         __half* __restrict__ bfh, __half* __restrict__ cfh,
                         __half* __restrict__ wc1t, __half* __restrict__ wc2t,
                         __half* __restrict__ wb2t,
                         __half* __restrict__ faLo, __half* __restrict__ faHi,
                         __half* __restrict__ b1Lo, __half* __restrict__ b1Hi)
{
    long long i = (long long)blockIdx.x * blockDim.x + threadIdx.x;
    if (i < SEG0) { bfh[i] = __float2half(bf[i]); return; }
    i -= SEG0;
    if (i < SEG1) { cfh[i] = __float2half(cf[i]); return; }
    i -= SEG1;
    if (i < SEG2) { wc1t[i] = pairT_elem(c1wl, c1wr, (int)i, 32, 512, 0); return; }
    i -= SEG2;
    if (i < SEG3) { wc2t[i] = pairT_elem(c2wl, c2wr, (int)i, 512, 128, 0); return; }
    i -= SEG3;
    if (i < SEG4) { wb2t[i] = pairT_elem(b2wl, b2wr, (int)i, 512, 128, 0); return; }
    i -= SEG4;
    if (i < SEG5) { faLo[i] = faT_elem(faw1, (int)i, 64, 0); return; }
    i -= SEG5;
    if (i < SEG6) { faHi[i] = faT_elem(faw1, (int)i, 128, 64); return; }
    i -= SEG6;
    if (i < SEG7) { b1Lo[i] = pairT_elem(b1wl, b1wr, (int)i, 64, 512, 0); return; }
    i -= SEG7;
    if (i < SEG8) { b1Hi[i] = pairT_elem(b1wl, b1wr, (int)i, 128, 512, 64); return; }
}

// Bucket lists store SRC node ids directly.
__global__ void build_lists(const int* __restrict__ ei, int E,
                            int* __restrict__ cnt, int* __restrict__ el)
{
    int e = blockIdx.x * blockDim.x + threadIdx.x;
    if (e >= E) return;
    int s = ei[e];
    int d = ei[E + e];
    int slot = atomicAdd(&cnt[d], 1);
    if (slot < CAP) el[(long long)d * CAP + slot] = s;
}

// ---------------------------------------------------------------------------
// FP16 tensor-core GEMM, m16n8k16, 3-stage cp.async pipeline, ldmatrix frags.
// C[N,M] = A[N,K] @ B^T  (B passed TRANSPOSED as [M,K] fp16, k contiguous)
// 128x128x32 CTA tile, 8 warps, warp tile 64x32.
// MODE 0: plain store (+bias, optional relu). CHALF: store fp16 vs fp32.
// MODE 1 (fa): epilogue v = relu(acc + Z[map[row]][col] + bias[col]);
//   head-reduce vs w2; softmax(+b2); atomicAdd 0.125*softmax into wmean.
// MODE 2 (b1): A fragments scaled by ascale[row*2+0] (half2 mul);
//   store C = acc + ascale[row*2+1] * Z[map[row]][col] (fp16).
// ---------------------------------------------------------------------------
#define ATILE_B (128 * 80)
#define BTILE_B (128 * 80)
#define BUF_B (ATILE_B + BTILE_B)
#define STAGES 3
#define GEMM_SMEM_BYTES (STAGES * BUF_B)   // 61440

__device__ __forceinline__ void cp16(uint32_t d, const void* s, bool pred) {
    int sz = pred ? 16 : 0;
    asm volatile("cp.async.ca.shared.global [%0], [%1], 16, %2;\n"
                 :: "r"(d), "l"(s), "r"(sz));
}

__device__ __forceinline__ void mma16(float* c, unsigned a0, unsigned a1,
                                      unsigned a2, unsigned a3,
                                      unsigned b0, unsigned b1) {
    asm volatile(
        "mma.sync.aligned.m16n8k16.row.col.f32.f16.f16.f32 "
        "{%0,%1,%2,%3},{%4,%5,%6,%7},{%8,%9},{%0,%1,%2,%3};"
        : "+f"(c[0]), "+f"(c[1]), "+f"(c[2]), "+f"(c[3])
        : "r"(a0), "r"(a1), "r"(a2), "r"(a3), "r"(b0), "r"(b1));
}

__device__ __forceinline__ void ldsm4(unsigned& r0, unsigned& r1,
                                      unsigned& r2, unsigned& r3, uint32_t addr) {
    asm volatile("ldmatrix.sync.aligned.m8n8.x4.shared.b16 {%0,%1,%2,%3}, [%4];"
                 : "=r"(r0), "=r"(r1), "=r"(r2), "=r"(r3) : "r"(addr));
}

__device__ __forceinline__ unsigned hmul2u(unsigned a, __half2 s) {
    __half2 v = __hmul2(*reinterpret_cast<__half2*>(&a), s);
    return *reinterpret_cast<unsigned*>(&v);
}

template<int MODE, bool CHALF>
__global__ void __launch_bounds__(256, 2) hgemm(
    const __half* __restrict__ A, const __half* __restrict__ B,
    void* __restrict__ Cv, const float* __restrict__ bias,
    int N, int K, int M, int relu,
    const float* __restrict__ w2, const float* __restrict__ b2,
    float* __restrict__ wmean,
    const float* __restrict__ zsrc,    // fp32 [NC, M] (MODE 1/2)
    const int*   __restrict__ gmap,    // [N]          (MODE 1/2)
    const float* __restrict__ ascale)  // fp32 [N,2]   (MODE 2)
{
    extern __shared__ char smc[];
    int tid = threadIdx.x;
    int warp = tid >> 5, lane = tid & 31;
    int wm = (warp >> 2) * 64;
    int wn = (warp & 3) * 32;
    int g  = lane >> 2;
    int tg = lane & 3;
    int rowBase = blockIdx.y * 128;
    int colBase = blockIdx.x * 128;

    uint32_t sbase = (uint32_t)__cvta_generic_to_shared(smc);

    int lrow = lane & 7, seg = lane >> 3;
    uint32_t aLane = (uint32_t)((wm + (seg & 1) * 8 + lrow) * 80 + ((seg >> 1) & 1) * 16);
    uint32_t bLane = (uint32_t)((wn + (seg >> 1) * 8 + lrow) * 80 + (seg & 1) * 16);

    float acc[4][4][4] = {};
    int T = K >> 5;

    // MODE 2: per-row wm0 scales as broadcast half2 (rows g and g+8 per mi)
    __half2 sc0[4], sc1[4];
    if (MODE == 2) {
        #pragma unroll
        for (int mi = 0; mi < 4; mi++) {
            int r0 = rowBase + wm + mi * 16 + g;
            int r1 = r0 + 8;
            sc0[mi] = __float2half2_rn(r0 < N ? ascale[(long long)r0 * 2] : 0.0f);
            sc1[mi] = __float2half2_rn(r1 < N ? ascale[(long long)r1 * 2] : 0.0f);
        }
    }

    auto issue_tile = [&](int k0, int buf) {
        uint32_t ab = sbase + (uint32_t)(buf * BUF_B);
        uint32_t bb = ab + ATILE_B;
        #pragma unroll
        for (int it = 0; it < 2; it++) {
            int c = tid + it * 256;
            int r  = c >> 2;
            int kc = (c & 3) << 3;
            int gr = rowBase + r;
            bool pa = gr < N;
            cp16(ab + (uint32_t)(r * 80 + kc * 2),
                 A + (long long)(pa ? gr : 0) * K + k0 + kc, pa);
            int n = colBase + r;
            cp16(bb + (uint32_t)(r * 80 + kc * 2),
                 B + (long long)n * K + k0 + kc, true);
        }
        asm volatile("cp.async.commit_group;\n");
    };

    issue_tile(0, 0);
    if (T > 1) issue_tile(32, 1);

    for (int t = 0; t < T; t++) {
        if (t + 1 < T) { asm volatile("cp.async.wait_group 1;\n"); }
        else           { asm volatile("cp.async.wait_group 0;\n"); }
        __syncthreads();
        if (t + 2 < T) issue_tile((t + 2) << 5, (t + 2) % STAGES);

        uint32_t ab = sbase + (uint32_t)((t % STAGES) * BUF_B);
        uint32_t aAddr = ab + aLane;
        uint32_t bAddr = ab + ATILE_B + bLane;

        #pragma unroll
        for (int ks = 0; ks < 32; ks += 16) {
            unsigned aF[4][4], bF[4][2];
            #pragma unroll
            for (int mi = 0; mi < 4; mi++) {
                ldsm4(aF[mi][0], aF[mi][1], aF[mi][2], aF[mi][3],
                      aAddr + (uint32_t)(mi * 16 * 80 + ks * 2));
                if (MODE == 2) {
                    aF[mi][0] = hmul2u(aF[mi][0], sc0[mi]);
                    aF[mi][1] = hmul2u(aF[mi][1], sc1[mi]);
                    aF[mi][2] = hmul2u(aF[mi][2], sc0[mi]);
                    aF[mi][3] = hmul2u(aF[mi][3], sc1[mi]);
                }
            }
            #pragma unroll
            for (int p = 0; p < 2; p++)
                ldsm4(bF[2 * p][0], bF[2 * p][1], bF[2 * p + 1][0], bF[2 * p + 1][1],
                      bAddr + (uint32_t)(p * 16 * 80 + ks * 2));
            #pragma unroll
            for (int mi = 0; mi < 4; mi++)
                #pragma unroll
                for (int nj = 0; nj < 4; nj++)
                    mma16(acc[mi][nj], aF[mi][0], aF[mi][1], aF[mi][2], aF[mi][3],
                          bF[nj][0], bF[nj][1]);
        }
    }

    if (MODE != 1) {
        #pragma unroll
        for (int mi = 0; mi < 4; mi++) {
            int row = rowBase + wm + mi * 16 + g;
            const float* z0p = nullptr; const float* z1p = nullptr;
            float w1a = 0.f, w1b = 0.f;
            if (MODE == 2) {
                if (row < N)     { z0p = zsrc + (long long)gmap[row] * M;
                                   w1a = ascale[(long long)row * 2 + 1]; }
                if (row + 8 < N) { z1p = zsrc + (long long)gmap[row + 8] * M;
                                   w1b = ascale[(long long)(row + 8) * 2 + 1]; }
            }
            #pragma unroll
            for (int nj = 0; nj < 4; nj++) {
                int col = colBase + wn + nj * 8 + tg * 2;
                float b0 = 0.f, b1 = 0.f;
                if (bias) { b0 = bias[col]; b1 = bias[col + 1]; }
                if (row < N) {
                    float vx = acc[mi][nj][0] + b0, vy = acc[mi][nj][1] + b1;
                    if (MODE == 2) {
                        float2 zv = *(const float2*)(z0p + col);
                        vx += w1a * zv.x; vy += w1a * zv.y;
                    }
                    if (relu) { vx = fmaxf(vx, 0.f); vy = fmaxf(vy, 0.f); }
                    if (CHALF) *(__half2*)((__half*)Cv + (long long)row * M + col) =
                                   __floats2half2_rn(vx, vy);
                    else       *(float2*)((float*)Cv + (long long)row * M + col) =
                                   make_float2(vx, vy);
                }
                if (row + 8 < N) {
                    float vx = acc[mi][nj][2] + b0, vy = acc[mi][nj][3] + b1;
                    if (MODE == 2) {
                        float2 zv = *(const float2*)(z1p + col);
                        vx += w1b * zv.x; vy += w1b * zv.y;
                    }
                    if (relu) { vx = fmaxf(vx, 0.f); vy = fmaxf(vy, 0.f); }
                    if (CHALF) *(__half2*)((__half*)Cv + (long long)(row + 8) * M + col) =
                                   __floats2half2_rn(vx, vy);
                    else       *(float2*)((float*)Cv + (long long)(row + 8) * M + col) =
                                   make_float2(vx, vy);
                }
            }
        }
    } else {
        // fa-head epilogue with Z add. head = blockIdx.x.
        int h = blockIdx.x;
        float* srow = (float*)smc;
        __syncthreads();
        for (int i = tid; i < 256; i += 256) srow[i] = 0.0f;
        __syncthreads();

        #pragma unroll
        for (int mi = 0; mi < 4; mi++) {
            #pragma unroll
            for (int hf = 0; hf < 2; hf++) {
                int rrel = wm + mi * 16 + g + 8 * hf;
                int row = rowBase + rrel;
                if (row >= N) continue;
                const float* zrow = zsrc + (long long)gmap[row] * M + colBase;
                float p0 = 0.f, p1 = 0.f;
                #pragma unroll
                for (int nj = 0; nj < 4; nj++) {
                    int cr = wn + nj * 8 + tg * 2;
                    float a0 = acc[mi][nj][2 * hf];
                    float a1 = acc[mi][nj][2 * hf + 1];
                    float v0 = fmaxf(a0 + zrow[cr] + bias[colBase + cr], 0.f);
                    float v1 = fmaxf(a1 + zrow[cr + 1] + bias[colBase + cr + 1], 0.f);
                    float2 wa = *(const float2*)(w2 + h * 256 + cr * 2);
                    float2 wb = *(const float2*)(w2 + h * 256 + (cr + 1) * 2);
                    p0 += v0 * wa.x + v1 * wb.x;
                    p1 += v0 * wa.y + v1 * wb.y;
                }
                atomicAdd(&srow[rrel * 2 + 0], p0);
                atomicAdd(&srow[rrel * 2 + 1], p1);
            }
        }
        __syncthreads();
        if (tid < 128) {
            int grow = rowBase + tid;
            if (grow < N) {
                float sa = srow[tid * 2 + 0] + b2[h * 2 + 0];
                float sb = srow[tid * 2 + 1] + b2[h * 2 + 1];
                float mx = fmaxf(sa, sb);
                float e0 = expf(sa - mx), e1 = expf(sb - mx);
                float inv = 0.125f / (e0 + e1);
                atomicAdd(&wmean[(long long)grow * 2 + 0], e0 * inv);
                atomicAdd(&wmean[(long long)grow * 2 + 1], e1 * inv);
            }
        }
    }
}

// ---------------------------------------------------------------------------
// Fused GATv2 softmax+aggregate, fp16 in/out, online softmax, 4 halfs/lane.
// ---------------------------------------------------------------------------
template<int LPG, int D, int H, bool RELU>
__global__ void gat_fused(const int* __restrict__ cnt, const int* __restrict__ el,
                          const __half* __restrict__ xl, const __half* __restrict__ xr,
                          int ldx,
                          const float* __restrict__ att, const float* __restrict__ bias,
                          __half* __restrict__ out, int Nnodes)
{
    static_assert(D == 4 * LPG, "");
    long long t = (long long)blockIdx.x * blockDim.x + threadIdx.x;
    long long gidx = t / LPG;
    int lane = (int)(t % LPG);
    if (gidx >= (long long)Nnodes * H) return;
    int dst = (int)(gidx / H), h = (int)(gidx % H);

    long long roff = (long long)dst * ldx + h * D + lane * 4;
    uint2 ur = *(const uint2*)(xr + roff);
    float2 xr01 = __half22float2(*reinterpret_cast<__half2*>(&ur.x));
    float2 xr23 = __half22float2(*reinterpret_cast<__half2*>(&ur.y));
    float4 a4  = *(const float4*)(att + (long long)h * D + lane * 4);

    int c = cnt[dst]; if (c > CAP) c = CAP;
    const int* lst = el + (long long)dst * CAP;

    float mx = -1e30f, wsum = 0.0f;
    float4 acc = make_float4(0.f, 0.f, 0.f, 0.f);

    for (int i = 0; i <= c; i++) {
        int src = (i == c) ? dst : lst[i];
        uint2 uv = *(const uint2*)(xl + (long long)src * ldx + h * D + lane * 4);
        float2 v01 = __half22float2(*reinterpret_cast<__half2*>(&uv.x));
        float2 v23 = __half22float2(*reinterpret_cast<__half2*>(&uv.y));
        float e0 = v01.x + xr01.x; e0 = e0 > 0.f ? e0 : 0.2f * e0;
        float e1 = v01.y + xr01.y; e1 = e1 > 0.f ? e1 : 0.2f * e1;
        float e2 = v23.x + xr23.x; e2 = e2 > 0.f ? e2 : 0.2f * e2;
        float e3 = v23.y + xr23.y; e3 = e3 > 0.f ? e3 : 0.2f * e3;
        float s = e0 * a4.x + e1 * a4.y + e2 * a4.z + e3 * a4.w;
        #pragma unroll
        for (int o = LPG / 2; o; o >>= 1) s += __shfl_xor_sync(0xffffffffu, s, o, LPG);
        if (s > mx) {
            float f = expf(mx - s);
            wsum *= f;
            acc.x *= f; acc.y *= f; acc.z *= f; acc.w *= f;
            mx = s;
        }
        float p = expf(s - mx);
        wsum += p;
        acc.x += p * v01.x; acc.y += p * v01.y; acc.z += p * v23.x; acc.w += p * v23.y;
    }

    float inv = 1.0f / wsum;
    const float* pb = bias + h * D + lane * 4;
    float o0 = acc.x * inv + pb[0];
    float o1 = acc.y * inv + pb[1];
    float o2 = acc.z * inv + pb[2];
    float o3 = acc.w * inv + pb[3];
    if (RELU) {
        o0 = fmaxf(o0, 0.f); o1 = fmaxf(o1, 0.f);
        o2 = fmaxf(o2, 0.f); o3 = fmaxf(o3, 0.f);
    }
    __half2 h01 = __floats2half2_rn(o0, o1);
    __half2 h23 = __floats2half2_rn(o2, o3);
    uint2 uo;
    uo.x = *reinterpret_cast<unsigned*>(&h01);
    uo.y = *reinterpret_cast<unsigned*>(&h23);
    *(uint2*)(out + ((long long)dst * H + h) * D + lane * 4) = uo;
}

// Layer 3 (H=1, D=2) fused with final log-softmax, writes d_out (fp32).
__global__ void gat3_lsm(const int* __restrict__ cnt, const int* __restrict__ el,
                         const float* __restrict__ xl, const float* __restrict__ xr,
                         const float* __restrict__ att, const float* __restrict__ bias,
                         float* __restrict__ out, int Nnodes)
{
    long long t = (long long)blockIdx.x * blockDim.x + threadIdx.x;
    long long gidx = t >> 1;
    int lane = (int)(t & 1);
    if (gidx >= Nnodes) return;
    int dst = (int)gidx;

    float xr_d = xr[(long long)dst * 2 + lane];
    float a_d  = att[lane];
    int c = cnt[dst]; if (c > CAP) c = CAP;
    const int* lst = el + (long long)dst * CAP;

    float mx = -1e30f, wsum = 0.0f, acc = 0.0f;
    for (int i = 0; i <= c; i++) {
        int src = (i == c) ? dst : lst[i];
        float xv = xl[(long long)src * 2 + lane];
        float v = xv + xr_d;
        v = v > 0.0f ? v : 0.2f * v;
        float s = v * a_d;
        s += __shfl_xor_sync(0xffffffffu, s, 1, 2);
        if (s > mx) {
            float f = expf(mx - s);
            wsum *= f; acc *= f; mx = s;
        }
        float p = expf(s - mx);
        wsum += p;
        acc += p * xv;
    }
    float v = acc / wsum + bias[lane];
    float o = __shfl_xor_sync(0xffffffffu, v, 1, 2);
    float m2 = fmaxf(v, o);
    float lse = m2 + logf(expf(v - m2) + expf(o - m2));
    out[(long long)dst * 2 + lane] = v - lse;
}

// ---------------------------------------------------------------------------
// layer-3 transforms, 8 lanes per node (coalesced): [N,128] fp16 @ [128,2]x2
__global__ void small_xform8(const __half* __restrict__ x, const float* __restrict__ wl,
                             const float* __restrict__ wr, float* __restrict__ xl,
                             float* __restrict__ xr, int N)
{
    long long t = (long long)blockIdx.x * blockDim.x + threadIdx.x;
    long long n = t >> 3;
    int l = (int)(t & 7);
    if (n >= N) return;
    const __half* px = x + n * 128 + l * 16;
    float a0 = 0, a1 = 0, b0 = 0, b1 = 0;
    #pragma unroll
    for (int k = 0; k < 16; k++) {
        float v = __half2float(px[k]);
        int kk = l * 16 + k;
        a0 += v * wl[kk * 2]; a1 += v * wl[kk * 2 + 1];
        b0 += v * wr[kk * 2]; b1 += v * wr[kk * 2 + 1];
    }
    #pragma unroll
    for (int o = 4; o; o >>= 1) {
        a0 += __shfl_xor_sync(0xffffffffu, a0, o, 8);
        a1 += __shfl_xor_sync(0xffffffffu, a1, o, 8);
        b0 += __shfl_xor_sync(0xffffffffu, b0, o, 8);
        b1 += __shfl_xor_sync(0xffffffffu, b1, o, 8);
    }
    if (l == 0) {
        xl[n * 2] = a0; xl[n * 2 + 1] = a1;
        xr[n * 2] = b0; xr[n * 2 + 1] = b1;
    }
}

// ---------------------------------------------------------------------------
static inline int cdivll(long long a, long long b) { return (int)((a + b - 1) / b); }

extern "C" void kernel_launch(void* const* d_in, const int* in_sizes, int n_in,
                              void* d_out, int out_size)
{
    int idx_bf = 0, idx_cf = 1, idx_bei, idx_cei, idx_map, base_w;
    if (in_sizes[2] == 2 * EB) { idx_bei = 2; idx_cei = 3; idx_map = 4; base_w = 5; }
    else                       { base_w = 2; idx_bei = 26; idx_cei = 27; idx_map = 28; }
    const float* bf  = (const float*)d_in[idx_bf];
    const float* cf  = (const float*)d_in[idx_cf];
    const int*   bei = (const int*)d_in[idx_bei];
    const int*   cei = (const int*)d_in[idx_cei];
    const int*   b2c = (const int*)d_in[idx_map];

    enum { C1WL, C1WR, C1ATT, C1B, C2WL, C2WR, C2ATT, C2B,
           FAW1, FAB1, FAW2, FAB2,
           B1WL, B1WR, B1ATT, B1B, B2WL, B2WR, B2ATT, B2B,
           B3WL, B3WR, B3ATT, B3B };
    const float* W[24];
    for (int i = 0; i < 24; i++) W[i] = (const float*)d_in[base_w + i];

    float* S;
    cudaGetSymbolAddress((void**)&S, g_scratch);
    cudaFuncSetAttribute(hgemm<0, true>,  cudaFuncAttributeMaxDynamicSharedMemorySize, GEMM_SMEM_BYTES);
    cudaFuncSetAttribute(hgemm<0, false>, cudaFuncAttributeMaxDynamicSharedMemorySize, GEMM_SMEM_BYTES);
    cudaFuncSetAttribute(hgemm<1, false>, cudaFuncAttributeMaxDynamicSharedMemorySize, GEMM_SMEM_BYTES);
    cudaFuncSetAttribute(hgemm<2, true>,  cudaFuncAttributeMaxDynamicSharedMemorySize, GEMM_SMEM_BYTES);

    __half* cfh   = (__half*)(S + O_CFH);
    __half* c_xlr = (__half*)(S + O_CXLR);
    __half* c_h1  = (__half*)(S + O_CH1);
    __half* c_xlr2= (__half*)(S + O_CXLR2);
    __half* c_h2  = (__half*)(S + O_CH2);
    __half* Wc1t  = (__half*)(S + O_WC1T);
    __half* Wc2t  = (__half*)(S + O_WC2T);
    __half* Wb2t  = (__half*)(S + O_WB2T);
    __half* faLo  = (__half*)(S + O_FALO);
    __half* faHi  = (__half*)(S + O_FAHI);
    __half* b1Lo  = (__half*)(S + O_B1LO);
    __half* b1Hi  = (__half*)(S + O_B1HI);
    __half* bfh   = (__half*)(S + O_BFH);
    float*  wmean = S + O_WM;
    float*  Zfa   = S + O_ZFA;
    float*  Zb1   = S + O_ZB1;
    __half* b_xlr = (__half*)(S + O_BXLR);
    __half* b_h1  = (__half*)(S + O_BH1);
    __half* b_h2  = (__half*)(S + O_BH2);
    float*  xl3   = S + O_XL3;
    float*  xr3   = S + O_XR3;
    int* bcnt = (int*)(S + O_BCNT);
    int* bel  = (int*)(S + O_BEL);
    int* ccnt = (int*)(S + O_CCNT);
    int* cel  = (int*)(S + O_CEL);

    // ---- Zeroing + graph prep + ALL weight/feature prep ----
    zero_misc<<<cdivll(2 * NB, 256), 256>>>(bcnt, ccnt, wmean);
    build_lists<<<cdivll(EC, 256), 256>>>(cei, EC, ccnt, cel);
    build_lists<<<cdivll(EB, 256), 256>>>(bei, EB, bcnt, bel);
    prep_all<<<cdivll(PREP_TOTAL, 256), 256>>>(
        bf, cf, W[C1WL], W[C1WR], W[C2WL], W[C2WR], W[B2WL], W[B2WR],
        W[FAW1], W[B1WL], W[B1WR],
        bfh, cfh, Wc1t, Wc2t, Wb2t, faLo, faHi, b1Lo, b1Hi);

    // ---- Community GNN ----
    {
        dim3 grid(1024 / 128, (NC + 127) / 128);
        hgemm<0, true><<<grid, 256, GEMM_SMEM_BYTES>>>(
            cfh, Wc1t, c_xlr, nullptr, NC, 32, 1024, 0,
            nullptr, nullptr, nullptr, nullptr, nullptr, nullptr);
    }
    gat_fused<16, 64, 8, true><<<cdivll((long long)NC * 8 * 16, 256), 256>>>(
        ccnt, cel, c_xlr, c_xlr + 512, 1024, W[C1ATT], W[C1B], c_h1, NC);

    {
        dim3 grid(256 / 128, (NC + 127) / 128);
        hgemm<0, true><<<grid, 256, GEMM_SMEM_BYTES>>>(
            c_h1, Wc2t, c_xlr2, nullptr, NC, 512, 256, 0,
            nullptr, nullptr, nullptr, nullptr, nullptr, nullptr);
    }
    gat_fused<8, 32, 4, true><<<cdivll((long long)NC * 4 * 8, 256), 256>>>(
        ccnt, cel, c_xlr2, c_xlr2 + 128, 256, W[C2ATT], W[C2B], c_h2, NC);

    // ---- Low-rank precompute: Z = c_h2 @ W_hi (fp32 out) ----
    {
        dim3 grid(1024 / 128, (NC + 127) / 128);
        hgemm<0, false><<<grid, 256, GEMM_SMEM_BYTES>>>(
            c_h2, faHi, Zfa, nullptr, NC, 128, 1024, 0,
            nullptr, nullptr, nullptr, nullptr, nullptr, nullptr);
        hgemm<0, false><<<grid, 256, GEMM_SMEM_BYTES>>>(
            c_h2, b1Hi, Zb1, nullptr, NC, 128, 1024, 0,
            nullptr, nullptr, nullptr, nullptr, nullptr, nullptr);
    }

    // ---- Feature attention: acc = bfh @ faLo; epilogue adds Zfa[map] ----
    {
        dim3 grid(1024 / 128, (NB + 127) / 128);
        hgemm<1, false><<<grid, 256, GEMM_SMEM_BYTES>>>(
            bfh, faLo, nullptr, W[FAB1], NB, 64, 1024, 1,
            W[FAW2], W[FAB2], wmean, Zfa, b2c, nullptr);
    }

    // ---- Building GNN (b1: A = bfh scaled by wm0 in-fragment) ----
    {
        dim3 grid(1024 / 128, (NB + 127) / 128);
        hgemm<2, true><<<grid, 256, GEMM_SMEM_BYTES>>>(
            bfh, b1Lo, b_xlr, nullptr, NB, 64, 1024, 0,
            nullptr, nullptr, nullptr, Zb1, b2c, wmean);
    }
    gat_fused<16, 64, 8, true><<<cdivll((long long)NB * 8 * 16, 256), 256>>>(
        bcnt, bel, b_xlr, b_xlr + 512, 1024, W[B1ATT], W[B1B], b_h1, NB);

    {
        dim3 grid(256 / 128, (NB + 127) / 128);
        hgemm<0, true><<<grid, 256, GEMM_SMEM_BYTES>>>(
            b_h1, Wb2t, b_xlr, nullptr, NB, 512, 256, 0,
            nullptr, nullptr, nullptr, nullptr, nullptr, nullptr);
    }
    gat_fused<8, 32, 4, true><<<cdivll((long long)NB * 4 * 8, 256), 256>>>(
        bcnt, bel, b_xlr, b_xlr + 128, 256, W[B2ATT], W[B2B], b_h2, NB);

    small_xform8<<<cdivll((long long)NB * 8, 256), 256>>>(b_h2, W[B3WL], W[B3WR], xl3, xr3, NB);
    gat3_lsm<<<cdivll((long long)NB * 2, 256), 256>>>(
        bcnt, bel, xl3, xr3, W[B3ATT], W[B3B], (float*)d_out, NB);
}